// round 15
// baseline (speedup 1.0000x reference)
#include <cuda_runtime.h>
#include <cstdint>

#define Bn 32
#define Cn 512
#define Nn 1600
#define NCn 20
#define NOUT 25
#define NGRP (Bn * NCn)
#define STRIDEF 32.0f
#define CONF_T 0.3f
#define NMS_T 0.5f
#define CAPK 256
#define CAPB 192

typedef unsigned long long ull;

// ---------------- scratch -----------------------------------------------------
__device__ float g_boxes[Bn * Nn * 4];
__device__ int   g_cnt[NGRP];
__device__ ull   g_keys[NGRP * CAPK];
// B fragments: [ks(64)][nt(4)][lane(32)] -> {bh0, bh1, bl0, bl1} (tf32 bits)
__device__ uint4 g_Bfrag[64 * 4 * 32];

// ---------------- helpers -----------------------------------------------------
__device__ __forceinline__ uint32_t tf32_of(float x) {
    uint32_t r; asm("cvt.rna.tf32.f32 %0, %1;" : "=r"(r) : "f"(x)); return r;
}
__device__ __forceinline__ float sigmoidf_(float x) { return 1.0f / (1.0f + expf(-x)); }

__device__ __forceinline__ void mma_tf32(float* d, uint32_t a0, uint32_t a1,
                                         uint32_t a2, uint32_t a3,
                                         uint32_t b0, uint32_t b1) {
    asm volatile(
        "mma.sync.aligned.m16n8k8.row.col.f32.tf32.tf32.f32 "
        "{%0,%1,%2,%3}, {%4,%5,%6,%7}, {%8,%9}, {%0,%1,%2,%3};"
        : "+f"(d[0]), "+f"(d[1]), "+f"(d[2]), "+f"(d[3])
        : "r"(a0), "r"(a1), "r"(a2), "r"(a3), "r"(b0), "r"(b1));
}

// ---------------- prep: bake B (weights) into tf32 hi/lo fragments -----------
__global__ void __launch_bounds__(256) prep_kernel(
    const float* __restrict__ wo, const float* __restrict__ wc,
    const float* __restrict__ wr)
{
    int e = blockIdx.x * 256 + threadIdx.x;      // 0..8191
    int lane = e & 31;
    int nt = (e >> 5) & 3;
    int ks = e >> 7;
    int col = nt * 8 + (lane >> 2);
    int k0 = ks * 8 + (lane & 3);

    float w0 = 0.f, w1 = 0.f;
    if (col == 0)       { w0 = wo[k0];                  w1 = wo[k0 + 4]; }
    else if (col <= 20) { w0 = wc[(col - 1) * Cn + k0];  w1 = wc[(col - 1) * Cn + k0 + 4]; }
    else if (col <= 24) { w0 = wr[(col - 21) * Cn + k0]; w1 = wr[(col - 21) * Cn + k0 + 4]; }

    uint32_t h0 = tf32_of(w0), h1 = tf32_of(w1);
    uint32_t l0 = tf32_of(w0 - __uint_as_float(h0));
    uint32_t l1 = tf32_of(w1 - __uint_as_float(h1));
    g_Bfrag[e] = make_uint4(h0, h1, l0, l1);
}

// ---------------- Kernel A: tf32 mma.sync head, pipelined A/B prefetch ------
// 400 blocks x 256 threads. Warp w: m16 tile = cells [blk*128+w*16, +16),
// 64 k8-steps over 512 channels, 32 outs. A prefetch depth 8, B depth 2.
extern __shared__ float smemA[];
#define D_STRIDE 34
#define F_BIAS  (128 * D_STRIDE)       // 4352
#define F_TOTAL (F_BIAS + 32)          // 4384 floats = 17536 B

__global__ void __launch_bounds__(256) head_kernel(
    const float* __restrict__ feat,
    const float* __restrict__ wo, const float* __restrict__ bo,
    const float* __restrict__ wc, const float* __restrict__ bc,
    const float* __restrict__ wr, const float* __restrict__ br,
    float* __restrict__ out)
{
    const int tid  = threadIdx.x;
    const int w    = tid >> 5;
    const int lane = tid & 31;
    const int g    = lane >> 2;
    const int tg   = lane & 3;
    float* Dsm  = smemA;
    float* bias = smemA + F_BIAS;

    if (tid < NOUT) {
        float v;
        if (tid == 0)        v = bo[0];
        else if (tid <= NCn) v = bc[tid - 1];
        else                 v = br[tid - 1 - NCn];
        bias[tid] = v;
    }

    const int rowA = blockIdx.x * 128 + w * 16 + g;
    const int rowB = rowA + 8;
    const int bA = rowA / Nn, bB = rowB / Nn;
    const float* pA = feat + (size_t)bA * Cn * Nn + (rowA - bA * Nn) + (size_t)tg * Nn;
    const float* pB = feat + (size_t)bB * Cn * Nn + (rowB - bB * Nn) + (size_t)tg * Nn;

    float acc[4][4];
#pragma unroll
    for (int nt = 0; nt < 4; nt++)
#pragma unroll
        for (int r = 0; r < 4; r++) acc[nt][r] = 0.0f;

    const uint4* gB = g_Bfrag + lane;

    // ---- pipeline prologue: A depth 8, B depth 1
    float fb[8][4];
#pragma unroll
    for (int s = 0; s < 8; s++) {
        fb[s][0] = pA[(size_t)(s * 8) * Nn];
        fb[s][1] = pB[(size_t)(s * 8) * Nn];
        fb[s][2] = pA[(size_t)(s * 8 + 4) * Nn];
        fb[s][3] = pB[(size_t)(s * 8 + 4) * Nn];
    }
    uint4 bb2[2][4];
#pragma unroll
    for (int nt = 0; nt < 4; nt++) bb2[0][nt] = gB[nt * 32];

#pragma unroll 1
    for (int kb = 0; kb < 8; kb++) {
#pragma unroll
        for (int u = 0; u < 8; u++) {
            const int ks  = kb * 8 + u;
            const int cur = u & 1, nxt = cur ^ 1;

            // prefetch B for ks+1 (clamped; L2-hot)
            const int ksn = (ks < 63) ? ks + 1 : 63;
#pragma unroll
            for (int nt = 0; nt < 4; nt++)
                bb2[nxt][nt] = gB[(ksn * 4 + nt) * 32];

            // consume current A stage
            float f0 = fb[u][0], f1 = fb[u][1], f2 = fb[u][2], f3 = fb[u][3];

            // prefetch A for ks+8 into the stage just consumed (clamped)
            const int ksa = (ks < 56) ? ks + 8 : ks;
            fb[u][0] = pA[(size_t)(ksa * 8) * Nn];
            fb[u][1] = pB[(size_t)(ksa * 8) * Nn];
            fb[u][2] = pA[(size_t)(ksa * 8 + 4) * Nn];
            fb[u][3] = pB[(size_t)(ksa * 8 + 4) * Nn];

            uint32_t ah0 = tf32_of(f0), ah1 = tf32_of(f1);
            uint32_t ah2 = tf32_of(f2), ah3 = tf32_of(f3);
            uint32_t al0 = tf32_of(f0 - __uint_as_float(ah0));
            uint32_t al1 = tf32_of(f1 - __uint_as_float(ah1));
            uint32_t al2 = tf32_of(f2 - __uint_as_float(ah2));
            uint32_t al3 = tf32_of(f3 - __uint_as_float(ah3));
#pragma unroll
            for (int nt = 0; nt < 4; nt++) {
                uint4 bb = bb2[cur][nt];
                mma_tf32(acc[nt], ah0, ah1, ah2, ah3, bb.x, bb.y);  // Ah*Bh
                mma_tf32(acc[nt], al0, al1, al2, al3, bb.x, bb.y);  // Al*Bh
                mma_tf32(acc[nt], ah0, ah1, ah2, ah3, bb.z, bb.w);  // Ah*Bl
            }
        }
    }

    // exchange D via smem: Dsm[cell_local * 34 + col]
    __syncthreads();
    {
        int rA = w * 16 + g;
#pragma unroll
        for (int nt = 0; nt < 4; nt++) {
            int c = nt * 8 + tg * 2;
            *(float2*)&Dsm[rA * D_STRIDE + c]       = make_float2(acc[nt][0], acc[nt][1]);
            *(float2*)&Dsm[(rA + 8) * D_STRIDE + c] = make_float2(acc[nt][2], acc[nt][3]);
        }
    }
    __syncthreads();

    // epilogue: one cell per thread (threads 0..127)
    if (tid < 128) {
        int cell = blockIdx.x * 128 + tid;
        int eb = cell / Nn;
        int n  = cell - eb * Nn;
        float rr[25];
#pragma unroll
        for (int o = 0; o < NOUT; o++)
            rr[o] = Dsm[tid * D_STRIDE + o] + bias[o];

        float sig_obj = sigmoidf_(rr[0]);
        float best = rr[1]; int lab = 0;
#pragma unroll
        for (int k = 1; k < NCn; k++)
            if (rr[1 + k] > best) { best = rr[1 + k]; lab = k; }
        float score = sqrtf(sig_obj * sigmoidf_(best));

        float gx = (float)(n % 40), gy = (float)(n / 40);
        float cx = (sigmoidf_(rr[21]) + gx) * STRIDEF;
        float cy = (sigmoidf_(rr[22]) + gy) * STRIDEF;
        float bw = expf(rr[23]) * STRIDEF;
        float bh = expf(rr[24]) * STRIDEF;

        int idx = eb * Nn + n;
        float4 bx = make_float4(cx - bw * 0.5f, cy - bh * 0.5f,
                                cx + bw * 0.5f, cy + bh * 0.5f);
        *(float4*)&g_boxes[idx * 4] = bx;
        out[Bn * Nn * 5 + idx] = (float)lab;    // labels region

        int grp = eb * NCn + lab;
        int pos = atomicAdd(&g_cnt[grp], 1);
        unsigned sb = __float_as_uint(score);   // score > 0 always
        if (pos < CAPK)
            g_keys[grp * CAPK + pos] = ((ull)(~sb) << 32) | (unsigned)n;
    }
}

// ---------------- Kernel B: block-per-group NMS (unchanged) -----------------
__global__ void __launch_bounds__(128) nms_kernel(float* __restrict__ out)
{
    __shared__ ull    k[CAPK];
    __shared__ ull    ks[CAPB];
    __shared__ float4 bx[CAPB];
    __shared__ ull    mk[CAPB * 3];
    __shared__ int    scnt;

    const int tid = threadIdx.x;
    const int grp = blockIdx.x;
    const int b   = grp / NCn;
    const int bIdx = b * Nn;

    int M = g_cnt[grp];
    if (M > CAPB) M = CAPB;
    if (tid == 0) scnt = 0;

    for (int t = tid; t < M; t += 128) k[t] = g_keys[grp * CAPK + t];
    __syncthreads();
    if (tid == 0) g_cnt[grp] = 0;

    // rank sort (keys unique)
    for (int t = tid; t < M; t += 128) {
        ull key = k[t];
        int r = 0;
#pragma unroll 4
        for (int j = 0; j < M; j++)
            r += (k[j] < key) ? 1 : 0;
        ks[r] = key;
    }
    __syncthreads();

    int mc_loc = 0;
    for (int t = tid; t < M; t += 128) {
        int n = (int)(ks[t] & 0xFFFFFFFFULL);
        bx[t] = *(const float4*)&g_boxes[(bIdx + n) * 4];
        float s = __uint_as_float(~(unsigned)(ks[t] >> 32));
        if (s > CONF_T) mc_loc++;
    }
    if (mc_loc) atomicAdd(&scnt, mc_loc);
    __syncthreads();
    const int Mc = scnt;

    for (int t = tid; t < M; t += 128) {
        ull m0 = 0, m1 = 0, m2 = 0;
        float4 A = bx[t];
        float areaA = (A.z - A.x) * (A.w - A.y);
#pragma unroll 4
        for (int j = 0; j < M; j++) {
            float4 Bv = bx[j];
            float x1 = fmaxf(A.x, Bv.x), y1 = fmaxf(A.y, Bv.y);
            float x2 = fminf(A.z, Bv.z), y2 = fminf(A.w, Bv.w);
            float inter = fmaxf(x2 - x1, 0.0f) * fmaxf(y2 - y1, 0.0f);
            float areaB = (Bv.z - Bv.x) * (Bv.w - Bv.y);
            float uni = areaA + areaB - inter;
            bool sup = (j > t) && (inter > NMS_T * uni);
            ull bit = sup ? (1ULL << (j & 63)) : 0ULL;
            if (j < 64)       m0 |= bit;
            else if (j < 128) m1 |= bit;
            else              m2 |= bit;
        }
        mk[t * 3 + 0] = m0; mk[t * 3 + 1] = m1; mk[t * 3 + 2] = m2;
    }
    __syncthreads();

    ull kp0 = (Mc <= 0) ? 0ULL : (Mc >= 64 ? ~0ULL : ((1ULL << Mc) - 1));
    int c1 = Mc - 64;
    ull kp1 = (c1 <= 0) ? 0ULL : (c1 >= 64 ? ~0ULL : ((1ULL << c1) - 1));
    int c2 = Mc - 128;
    ull kp2 = (c2 <= 0) ? 0ULL : (c2 >= 64 ? ~0ULL : ((1ULL << c2) - 1));

#pragma unroll 4
    for (int i = 0; i < Mc; i++) {
        ull m0 = mk[i * 3 + 0], m1 = mk[i * 3 + 1], m2 = mk[i * 3 + 2];
        ull kw = (i < 64) ? kp0 : (i < 128) ? kp1 : kp2;
        if ((kw >> (i & 63)) & 1ULL) {
            kp0 &= ~m0; kp1 &= ~m1; kp2 &= ~m2;
        }
    }

    for (int t = tid; t < M; t += 128) {
        int n = (int)(ks[t] & 0xFFFFFFFFULL);
        int idx = bIdx + n;
        ull kw = (t < 64) ? kp0 : (t < 128) ? kp1 : kp2;
        bool kept = (kw >> (t & 63)) & 1ULL;
        float s = __uint_as_float(~(unsigned)(ks[t] >> 32));
        float4 Bv = bx[t];
        out[idx * 5 + 0] = kept ? Bv.x : 0.0f;
        out[idx * 5 + 1] = kept ? Bv.y : 0.0f;
        out[idx * 5 + 2] = kept ? Bv.z : 0.0f;
        out[idx * 5 + 3] = kept ? Bv.w : 0.0f;
        out[idx * 5 + 4] = kept ? s : 0.0f;
        out[Bn * Nn * 6 + idx] = kept ? 1.0f : 0.0f;
    }
}

// ---------------- launch -----------------------------------------------------
extern "C" void kernel_launch(void* const* d_in, const int* in_sizes, int n_in,
                              void* d_out, int out_size)
{
    const float* feat = (const float*)d_in[0];
    const float* wo   = (const float*)d_in[1];
    const float* bo   = (const float*)d_in[2];
    const float* wc   = (const float*)d_in[3];
    const float* bc   = (const float*)d_in[4];
    const float* wr   = (const float*)d_in[5];
    const float* br   = (const float*)d_in[6];
    float* out = (float*)d_out;

    size_t smem = (size_t)F_TOTAL * sizeof(float);   // 17536 B
    cudaFuncSetAttribute(head_kernel,
                         cudaFuncAttributeMaxDynamicSharedMemorySize, (int)smem);

    prep_kernel<<<32, 256>>>(wo, wc, wr);
    head_kernel<<<400, 256, smem>>>(feat, wo, bo, wc, bc, wr, br, out);
    nms_kernel<<<NGRP, 128>>>(out);
}

// round 16
// speedup vs baseline: 1.0956x; 1.0956x over previous
#include <cuda_runtime.h>
#include <cstdint>

#define Bn 32
#define Cn 512
#define Nn 1600
#define NCn 20
#define NOUT 25
#define NGRP (Bn * NCn)
#define STRIDEF 32.0f
#define CONF_T 0.3f
#define NMS_T 0.5f
#define CAPK 256
#define CAPB 192

typedef unsigned long long ull;

// ---------------- scratch -----------------------------------------------------
__device__ float g_boxes[Bn * Nn * 4];
__device__ int   g_cnt[NGRP];
__device__ ull   g_keys[NGRP * CAPK];
// B fragments (bf16 m16n8k16): [ks(32)][nt(4)][lane(32)] -> {bh0,bh1,bl0,bl1}
__device__ uint4 g_Bfrag[32 * 4 * 32];

// ---------------- helpers -----------------------------------------------------
__device__ __forceinline__ uint32_t bf16x2_of(float lo, float hi) {
    uint32_t r;
    asm("cvt.rn.bf16x2.f32 %0, %1, %2;" : "=r"(r) : "f"(hi), "f"(lo));
    return r;   // low 16 = lo, high 16 = hi
}
__device__ __forceinline__ float sigmoidf_(float x) { return 1.0f / (1.0f + expf(-x)); }

__device__ __forceinline__ void mma_bf16(float* d, uint32_t a0, uint32_t a1,
                                         uint32_t a2, uint32_t a3,
                                         uint32_t b0, uint32_t b1) {
    asm volatile(
        "mma.sync.aligned.m16n8k16.row.col.f32.bf16.bf16.f32 "
        "{%0,%1,%2,%3}, {%4,%5,%6,%7}, {%8,%9}, {%0,%1,%2,%3};"
        : "+f"(d[0]), "+f"(d[1]), "+f"(d[2]), "+f"(d[3])
        : "r"(a0), "r"(a1), "r"(a2), "r"(a3), "r"(b0), "r"(b1));
}

// ---------------- prep: bake B (weights) into bf16 hi/lo k16 fragments ------
// entry e: lane=e&31, nt=(e>>5)&3, ks=e>>7. col = nt*8 + (lane>>2);
// k0 = ks*16 + (lane&3)*2; b0 packs (k0,k0+1), b1 packs (k0+8,k0+9).
__global__ void __launch_bounds__(256) prep_kernel(
    const float* __restrict__ wo, const float* __restrict__ wc,
    const float* __restrict__ wr)
{
    int e = blockIdx.x * 256 + threadIdx.x;      // 0..4095
    int lane = e & 31;
    int nt = (e >> 5) & 3;
    int ks = e >> 7;
    int col = nt * 8 + (lane >> 2);
    int k0 = ks * 16 + (lane & 3) * 2;

    const float* row = 0;
    if (col == 0)       row = wo;
    else if (col <= 20) row = wc + (col - 1) * Cn;
    else if (col <= 24) row = wr + (col - 21) * Cn;

    float w00 = 0.f, w01 = 0.f, w10 = 0.f, w11 = 0.f;
    if (row) { w00 = row[k0]; w01 = row[k0 + 1]; w10 = row[k0 + 8]; w11 = row[k0 + 9]; }

    uint32_t bh0 = bf16x2_of(w00, w01);
    uint32_t bh1 = bf16x2_of(w10, w11);
    uint32_t bl0 = bf16x2_of(w00 - __uint_as_float(bh0 << 16),
                             w01 - __uint_as_float(bh0 & 0xFFFF0000u));
    uint32_t bl1 = bf16x2_of(w10 - __uint_as_float(bh1 << 16),
                             w11 - __uint_as_float(bh1 & 0xFFFF0000u));
    g_Bfrag[e] = make_uint4(bh0, bh1, bl0, bl1);
}

// ---------------- Kernel A: bf16 m16n8k16 head, A direct from gmem ----------
// 400 blocks x 256 threads. Warp w: m16 tile = cells [blk*128+w*16, +16),
// 32 k16-steps over 512 channels, 32 outs (25 real). No smem in main loop.
extern __shared__ float smemA[];
#define D_STRIDE 34
#define F_BIAS  (128 * D_STRIDE)       // 4352
#define F_TOTAL (F_BIAS + 32)          // 4384 floats = 17536 B

__global__ void __launch_bounds__(256) head_kernel(
    const float* __restrict__ feat,
    const float* __restrict__ wo, const float* __restrict__ bo,
    const float* __restrict__ wc, const float* __restrict__ bc,
    const float* __restrict__ wr, const float* __restrict__ br,
    float* __restrict__ out)
{
    const int tid  = threadIdx.x;
    const int w    = tid >> 5;
    const int lane = tid & 31;
    const int g    = lane >> 2;
    const int tg   = lane & 3;
    float* Dsm  = smemA;
    float* bias = smemA + F_BIAS;

    if (tid < NOUT) {
        float v;
        if (tid == 0)        v = bo[0];
        else if (tid <= NCn) v = bc[tid - 1];
        else                 v = br[tid - 1 - NCn];
        bias[tid] = v;
    }

    // rows g and g+8 of this warp's m16 tile (rows may straddle batches)
    const int rowA = blockIdx.x * 128 + w * 16 + g;
    const int rowB = rowA + 8;
    const int bA = rowA / Nn, bB = rowB / Nn;
    // include this lane's k offset (tg*2) in the base pointer
    const float* pA = feat + (size_t)bA * Cn * Nn + (rowA - bA * Nn)
                           + (size_t)(tg * 2) * Nn;
    const float* pB = feat + (size_t)bB * Cn * Nn + (rowB - bB * Nn)
                           + (size_t)(tg * 2) * Nn;

    float acc[4][4];
#pragma unroll
    for (int nt = 0; nt < 4; nt++)
#pragma unroll
        for (int r = 0; r < 4; r++) acc[nt][r] = 0.0f;

    const uint4* gB = g_Bfrag + lane;

#pragma unroll 2
    for (int ks = 0; ks < 32; ks++) {
        const float* qA = pA + (size_t)(ks * 16) * Nn;
        const float* qB = pB + (size_t)(ks * 16) * Nn;
        // A fragment rows g / g+8, k = tg*2,+1 and tg*2+8,+9
        float f0 = qA[0],          f1 = qA[Nn];
        float f2 = qA[8 * Nn],     f3 = qA[9 * Nn];
        float h0 = qB[0],          h1 = qB[Nn];
        float h2 = qB[8 * Nn],     h3 = qB[9 * Nn];

        uint32_t ah0 = bf16x2_of(f0, f1);
        uint32_t ah1 = bf16x2_of(h0, h1);
        uint32_t ah2 = bf16x2_of(f2, f3);
        uint32_t ah3 = bf16x2_of(h2, h3);
        uint32_t al0 = bf16x2_of(f0 - __uint_as_float(ah0 << 16),
                                 f1 - __uint_as_float(ah0 & 0xFFFF0000u));
        uint32_t al1 = bf16x2_of(h0 - __uint_as_float(ah1 << 16),
                                 h1 - __uint_as_float(ah1 & 0xFFFF0000u));
        uint32_t al2 = bf16x2_of(f2 - __uint_as_float(ah2 << 16),
                                 f3 - __uint_as_float(ah2 & 0xFFFF0000u));
        uint32_t al3 = bf16x2_of(h2 - __uint_as_float(ah3 << 16),
                                 h3 - __uint_as_float(ah3 & 0xFFFF0000u));

#pragma unroll
        for (int nt = 0; nt < 4; nt++) {
            uint4 bb = gB[(ks * 4 + nt) * 32];
            mma_bf16(acc[nt], ah0, ah1, ah2, ah3, bb.x, bb.y);   // Ah*Bh
            mma_bf16(acc[nt], al0, al1, al2, al3, bb.x, bb.y);   // Al*Bh
            mma_bf16(acc[nt], ah0, ah1, ah2, ah3, bb.z, bb.w);   // Ah*Bl
        }
    }

    // exchange D via smem: Dsm[cell_local * 34 + col]
    __syncthreads();
    {
        int rA = w * 16 + g;
#pragma unroll
        for (int nt = 0; nt < 4; nt++) {
            int c = nt * 8 + tg * 2;
            *(float2*)&Dsm[rA * D_STRIDE + c]       = make_float2(acc[nt][0], acc[nt][1]);
            *(float2*)&Dsm[(rA + 8) * D_STRIDE + c] = make_float2(acc[nt][2], acc[nt][3]);
        }
    }
    __syncthreads();

    // epilogue: one cell per thread (threads 0..127)
    if (tid < 128) {
        int cell = blockIdx.x * 128 + tid;
        int eb = cell / Nn;
        int n  = cell - eb * Nn;
        float rr[25];
#pragma unroll
        for (int o = 0; o < NOUT; o++)
            rr[o] = Dsm[tid * D_STRIDE + o] + bias[o];

        float sig_obj = sigmoidf_(rr[0]);
        float best = rr[1]; int lab = 0;
#pragma unroll
        for (int k = 1; k < NCn; k++)
            if (rr[1 + k] > best) { best = rr[1 + k]; lab = k; }
        float score = sqrtf(sig_obj * sigmoidf_(best));

        float gx = (float)(n % 40), gy = (float)(n / 40);
        float cx = (sigmoidf_(rr[21]) + gx) * STRIDEF;
        float cy = (sigmoidf_(rr[22]) + gy) * STRIDEF;
        float bw = expf(rr[23]) * STRIDEF;
        float bh = expf(rr[24]) * STRIDEF;

        int idx = eb * Nn + n;
        float4 bx = make_float4(cx - bw * 0.5f, cy - bh * 0.5f,
                                cx + bw * 0.5f, cy + bh * 0.5f);
        *(float4*)&g_boxes[idx * 4] = bx;
        out[Bn * Nn * 5 + idx] = (float)lab;    // labels region

        int grp = eb * NCn + lab;
        int pos = atomicAdd(&g_cnt[grp], 1);
        unsigned sb = __float_as_uint(score);   // score > 0 always
        if (pos < CAPK)
            g_keys[grp * CAPK + pos] = ((ull)(~sb) << 32) | (unsigned)n;
    }
}

// ---------------- Kernel B: block-per-group NMS (leaner mask loop) ----------
__global__ void __launch_bounds__(128) nms_kernel(float* __restrict__ out)
{
    __shared__ ull    k[CAPK];
    __shared__ ull    ks[CAPB];
    __shared__ float4 bx[CAPB];
    __shared__ float  ar[CAPB];
    __shared__ ull    mk[CAPB * 3];
    __shared__ int    scnt;

    const int tid = threadIdx.x;
    const int grp = blockIdx.x;
    const int b   = grp / NCn;
    const int bIdx = b * Nn;

    int M = g_cnt[grp];
    if (M > CAPB) M = CAPB;
    if (tid == 0) scnt = 0;

    for (int t = tid; t < M; t += 128) k[t] = g_keys[grp * CAPK + t];
    __syncthreads();
    if (tid == 0) g_cnt[grp] = 0;

    // rank sort (keys unique)
    for (int t = tid; t < M; t += 128) {
        ull key = k[t];
        int r = 0;
#pragma unroll 4
        for (int j = 0; j < M; j++)
            r += (k[j] < key) ? 1 : 0;
        ks[r] = key;
    }
    __syncthreads();

    int mc_loc = 0;
    for (int t = tid; t < M; t += 128) {
        int n = (int)(ks[t] & 0xFFFFFFFFULL);
        float4 Bv = *(const float4*)&g_boxes[(bIdx + n) * 4];
        bx[t] = Bv;
        ar[t] = (Bv.z - Bv.x) * (Bv.w - Bv.y);
        float s = __uint_as_float(~(unsigned)(ks[t] >> 32));
        if (s > CONF_T) mc_loc++;
    }
    if (mc_loc) atomicAdd(&scnt, mc_loc);
    __syncthreads();
    const int Mc = scnt;

    // suppression bitmasks: upper triangle, word-block hoisted out of inner loop
    for (int t = tid; t < M; t += 128) {
        float4 A = bx[t];
        float areaA = ar[t];
#pragma unroll
        for (int wb = 0; wb < 3; wb++) {
            int j0 = wb << 6;
            int js = (t + 1 > j0) ? t + 1 : j0;
            int je = (M < j0 + 64) ? M : j0 + 64;
            ull m = 0;
#pragma unroll 4
            for (int j = js; j < je; j++) {
                float4 Bv = bx[j];
                float x1 = fmaxf(A.x, Bv.x), y1 = fmaxf(A.y, Bv.y);
                float x2 = fminf(A.z, Bv.z), y2 = fminf(A.w, Bv.w);
                float inter = fmaxf(x2 - x1, 0.0f) * fmaxf(y2 - y1, 0.0f);
                float uni = areaA + ar[j] - inter;
                if (inter > NMS_T * uni) m |= 1ULL << (j - j0);
            }
            mk[t * 3 + wb] = m;
        }
    }
    __syncthreads();

    // serial mask reduction, replicated on all threads (broadcast LDS)
    ull kp0 = (Mc <= 0) ? 0ULL : (Mc >= 64 ? ~0ULL : ((1ULL << Mc) - 1));
    int c1 = Mc - 64;
    ull kp1 = (c1 <= 0) ? 0ULL : (c1 >= 64 ? ~0ULL : ((1ULL << c1) - 1));
    int c2 = Mc - 128;
    ull kp2 = (c2 <= 0) ? 0ULL : (c2 >= 64 ? ~0ULL : ((1ULL << c2) - 1));

#pragma unroll 4
    for (int i = 0; i < Mc; i++) {
        ull m0 = mk[i * 3 + 0], m1 = mk[i * 3 + 1], m2 = mk[i * 3 + 2];
        ull kw = (i < 64) ? kp0 : (i < 128) ? kp1 : kp2;
        if ((kw >> (i & 63)) & 1ULL) {
            kp0 &= ~m0; kp1 &= ~m1; kp2 &= ~m2;
        }
    }

    for (int t = tid; t < M; t += 128) {
        int n = (int)(ks[t] & 0xFFFFFFFFULL);
        int idx = bIdx + n;
        ull kw = (t < 64) ? kp0 : (t < 128) ? kp1 : kp2;
        bool kept = (kw >> (t & 63)) & 1ULL;
        float s = __uint_as_float(~(unsigned)(ks[t] >> 32));
        float4 Bv = bx[t];
        out[idx * 5 + 0] = kept ? Bv.x : 0.0f;
        out[idx * 5 + 1] = kept ? Bv.y : 0.0f;
        out[idx * 5 + 2] = kept ? Bv.z : 0.0f;
        out[idx * 5 + 3] = kept ? Bv.w : 0.0f;
        out[idx * 5 + 4] = kept ? s : 0.0f;
        out[Bn * Nn * 6 + idx] = kept ? 1.0f : 0.0f;
    }
}

// ---------------- launch -----------------------------------------------------
extern "C" void kernel_launch(void* const* d_in, const int* in_sizes, int n_in,
                              void* d_out, int out_size)
{
    const float* feat = (const float*)d_in[0];
    const float* wo   = (const float*)d_in[1];
    const float* bo   = (const float*)d_in[2];
    const float* wc   = (const float*)d_in[3];
    const float* bc   = (const float*)d_in[4];
    const float* wr   = (const float*)d_in[5];
    const float* br   = (const float*)d_in[6];
    float* out = (float*)d_out;

    size_t smem = (size_t)F_TOTAL * sizeof(float);   // 17536 B
    cudaFuncSetAttribute(head_kernel,
                         cudaFuncAttributeMaxDynamicSharedMemorySize, (int)smem);

    prep_kernel<<<16, 256>>>(wo, wc, wr);
    head_kernel<<<400, 256, smem>>>(feat, wo, bo, wc, bc, wr, br, out);
    nms_kernel<<<NGRP, 128>>>(out);
}

// round 17
// speedup vs baseline: 1.2129x; 1.1071x over previous
#include <cuda_runtime.h>
#include <cstdint>

#define Bn 32
#define Cn 512
#define Nn 1600
#define NCn 20
#define NOUT 25
#define NGRP (Bn * NCn)
#define STRIDEF 32.0f
#define CONF_T 0.3f
#define NMS_T 0.5f
#define CAPK 256
#define CAPB 192

typedef unsigned long long ull;

// ---------------- scratch (device globals; zero-initialized at load) --------
__device__ float g_boxes[Bn * Nn * 4];
__device__ int   g_cnt[NGRP];
__device__ ull   g_keys[NGRP * CAPK];

// ---------------- helpers ----------------------------------------------------
__device__ __forceinline__ ull pack2(float x, float y) {
    ull r; asm("mov.b64 %0, {%1, %2};" : "=l"(r) : "f"(x), "f"(y)); return r;
}
__device__ __forceinline__ void fma2(ull& d, ull a, ull b) {
    asm("fma.rn.f32x2 %0, %1, %2, %0;" : "+l"(d) : "l"(a), "l"(b));
}
__device__ __forceinline__ float2 unpack2(ull v) {
    float2 r; asm("mov.b64 {%0, %1}, %2;" : "=f"(r.x), "=f"(r.y) : "l"(v)); return r;
}
__device__ __forceinline__ float sigmoidf_(float x) { return 1.0f / (1.0f + expf(-x)); }

// ---------------- Kernel A: head (R12 verbatim) ------------------------------
// 2 cells/thread x split-K(4), 400 blocks x 256 threads. Weight smem
// ws[c*28+o]: 6x LDS.128 + 1x LDS.32 per channel feed 24 FFMA2 + 2 FFMA.
extern __shared__ float smemA[];
#define TBH 256
#define W_STRIDE 28
#define P_STRIDE 27
#define P_Q      3456
#define F_PART_BASE 0
#define F_BIAS   14336
#define F_TOTAL  14368

__global__ void __launch_bounds__(TBH) head_kernel(
    const float* __restrict__ feat,
    const float* __restrict__ wo, const float* __restrict__ bo,
    const float* __restrict__ wc, const float* __restrict__ bc,
    const float* __restrict__ wr, const float* __restrict__ br,
    float* __restrict__ out)
{
    float* ws   = smemA;
    float* bias = smemA + F_BIAS;
    const int tid = threadIdx.x;

    for (int i = tid; i < (Cn / 4) * NOUT; i += TBH) {
        int o  = i >> 7;
        int cq = i & 127;
        const float* row;
        if (o == 0)       row = wo;
        else if (o <= 20) row = wc + (o - 1) * Cn;
        else              row = wr + (o - 21) * Cn;
        float4 w4 = ((const float4*)row)[cq];
        int c = cq * 4;
        ws[(c + 0) * W_STRIDE + o] = w4.x;
        ws[(c + 1) * W_STRIDE + o] = w4.y;
        ws[(c + 2) * W_STRIDE + o] = w4.z;
        ws[(c + 3) * W_STRIDE + o] = w4.w;
    }
    if (tid < NOUT) {
        float v;
        if (tid == 0)        v = bo[0];
        else if (tid <= NCn) v = bc[tid - 1];
        else                 v = br[tid - 1 - NCn];
        bias[tid] = v;
    }
    __syncthreads();

    const int q    = tid >> 6;
    const int slot = tid & 63;
    const int cell0 = blockIdx.x * 128 + slot * 2;
    const int b  = cell0 / Nn;
    const int n0 = cell0 - b * Nn;
    const float2* fp2 = (const float2*)(feat + (size_t)b * Cn * Nn
                                             + (size_t)q * 128 * Nn + n0);
    const int cb = q * 128;

    ull acc[2][12];
    float a24[2] = {0.0f, 0.0f};
#pragma unroll
    for (int cc = 0; cc < 2; cc++)
#pragma unroll
        for (int p = 0; p < 12; p++) acc[cc][p] = 0ULL;

#pragma unroll 1
    for (int c0 = 0; c0 < 128; c0 += 8) {
        float2 v[8];
#pragma unroll
        for (int u = 0; u < 8; u++) v[u] = fp2[(c0 + u) * (Nn / 2)];
#pragma unroll
        for (int u = 0; u < 8; u++) {
            ull xx = pack2(v[u].x, v[u].x);
            ull yy = pack2(v[u].y, v[u].y);
            const float* wc_ = ws + (cb + c0 + u) * W_STRIDE;
#pragma unroll
            for (int qd = 0; qd < 6; qd++) {
                const uint4 w4 = *(const uint4*)(wc_ + qd * 4);
                ull w01 = ((ull)w4.y << 32) | w4.x;
                ull w23 = ((ull)w4.w << 32) | w4.z;
                fma2(acc[0][2 * qd],     xx, w01);
                fma2(acc[1][2 * qd],     yy, w01);
                fma2(acc[0][2 * qd + 1], xx, w23);
                fma2(acc[1][2 * qd + 1], yy, w23);
            }
            float w24 = wc_[24];
            a24[0] = fmaf(v[u].x, w24, a24[0]);
            a24[1] = fmaf(v[u].y, w24, a24[1]);
        }
    }

    __syncthreads();
#pragma unroll
    for (int cc = 0; cc < 2; cc++) {
        int cl = slot * 2 + cc;
        float* dst = smemA + F_PART_BASE + q * P_Q + cl * P_STRIDE;
#pragma unroll
        for (int p = 0; p < 12; p++) {
            float2 t = unpack2(acc[cc][p]);
            dst[2 * p]     = t.x;
            dst[2 * p + 1] = t.y;
        }
        dst[24] = a24[cc];
    }
    __syncthreads();

    if (tid < 128) {
        int cl = tid;
        int cell = blockIdx.x * 128 + cl;
        int eb = cell / Nn;
        int n  = cell - eb * Nn;
        float rr[25];
#pragma unroll
        for (int o = 0; o < NOUT; o++)
            rr[o] = smemA[F_PART_BASE + 0 * P_Q + cl * P_STRIDE + o]
                  + smemA[F_PART_BASE + 1 * P_Q + cl * P_STRIDE + o]
                  + smemA[F_PART_BASE + 2 * P_Q + cl * P_STRIDE + o]
                  + smemA[F_PART_BASE + 3 * P_Q + cl * P_STRIDE + o]
                  + bias[o];

        float sig_obj = sigmoidf_(rr[0]);
        float best = rr[1]; int lab = 0;
#pragma unroll
        for (int k = 1; k < NCn; k++)
            if (rr[1 + k] > best) { best = rr[1 + k]; lab = k; }
        float score = sqrtf(sig_obj * sigmoidf_(best));

        float gx = (float)(n % 40), gy = (float)(n / 40);
        float cx = (sigmoidf_(rr[21]) + gx) * STRIDEF;
        float cy = (sigmoidf_(rr[22]) + gy) * STRIDEF;
        float bw = expf(rr[23]) * STRIDEF;
        float bh = expf(rr[24]) * STRIDEF;

        int idx = eb * Nn + n;
        float4 bx = make_float4(cx - bw * 0.5f, cy - bh * 0.5f,
                                cx + bw * 0.5f, cy + bh * 0.5f);
        *(float4*)&g_boxes[idx * 4] = bx;
        out[Bn * Nn * 5 + idx] = (float)lab;

        int grp = eb * NCn + lab;
        int pos = atomicAdd(&g_cnt[grp], 1);
        unsigned sb = __float_as_uint(score);
        if (pos < CAPK)
            g_keys[grp * CAPK + pos] = ((ull)(~sb) << 32) | (unsigned)n;
    }
}

// ---------------- Kernel B: block-per-group NMS (trimmed) -------------------
__global__ void __launch_bounds__(128) nms_kernel(float* __restrict__ out)
{
    __shared__ ull    k[CAPK];
    __shared__ ull    ks[CAPB];
    __shared__ float4 bx[CAPB];
    __shared__ float  ar[CAPB];
    __shared__ ull    mk[CAPB * 3];
    __shared__ int    scnt;

    const int tid = threadIdx.x;
    const int grp = blockIdx.x;
    const int b   = grp / NCn;
    const int bIdx = b * Nn;

    int M = g_cnt[grp];
    if (M > CAPB) M = CAPB;
    if (tid == 0) scnt = 0;

    for (int t = tid; t < M; t += 128) k[t] = g_keys[grp * CAPK + t];
    __syncthreads();
    if (tid == 0) g_cnt[grp] = 0;

    // rank sort (keys unique), unrolled 8
    for (int t = tid; t < M; t += 128) {
        ull key = k[t];
        int r = 0;
#pragma unroll 8
        for (int j = 0; j < M; j++)
            r += (k[j] < key) ? 1 : 0;
        ks[r] = key;
    }
    __syncthreads();

    int mc_loc = 0;
    for (int t = tid; t < M; t += 128) {
        int n = (int)(ks[t] & 0xFFFFFFFFULL);
        float4 Bv = *(const float4*)&g_boxes[(bIdx + n) * 4];
        bx[t] = Bv;
        ar[t] = (Bv.z - Bv.x) * (Bv.w - Bv.y);
        float s = __uint_as_float(~(unsigned)(ks[t] >> 32));
        if (s > CONF_T) mc_loc++;
    }
    if (mc_loc) atomicAdd(&scnt, mc_loc);
    __syncthreads();
    const int Mc = scnt;

    // suppression bitmasks, upper triangle; word-block hoisted
    for (int t = tid; t < M; t += 128) {
        float4 A = bx[t];
        float areaA = ar[t];
#pragma unroll
        for (int wb = 0; wb < 3; wb++) {
            int j0 = wb << 6;
            int js = (t + 1 > j0) ? t + 1 : j0;
            int je = (M < j0 + 64) ? M : j0 + 64;
            ull m = 0;
#pragma unroll 4
            for (int j = js; j < je; j++) {
                float4 Bv = bx[j];
                float x1 = fmaxf(A.x, Bv.x), y1 = fmaxf(A.y, Bv.y);
                float x2 = fminf(A.z, Bv.z), y2 = fminf(A.w, Bv.w);
                float inter = fmaxf(x2 - x1, 0.0f) * fmaxf(y2 - y1, 0.0f);
                float uni = areaA + ar[j] - inter;
                if (inter > NMS_T * uni) m |= 1ULL << (j - j0);
            }
            mk[t * 3 + wb] = m;
        }
    }
    __syncthreads();

    // serial mask reduction, replicated on all threads (broadcast LDS)
    ull kp0 = (Mc <= 0) ? 0ULL : (Mc >= 64 ? ~0ULL : ((1ULL << Mc) - 1));
    int c1 = Mc - 64;
    ull kp1 = (c1 <= 0) ? 0ULL : (c1 >= 64 ? ~0ULL : ((1ULL << c1) - 1));
    int c2 = Mc - 128;
    ull kp2 = (c2 <= 0) ? 0ULL : (c2 >= 64 ? ~0ULL : ((1ULL << c2) - 1));

#pragma unroll 4
    for (int i = 0; i < Mc; i++) {
        ull m0 = mk[i * 3 + 0], m1 = mk[i * 3 + 1], m2 = mk[i * 3 + 2];
        ull kw = (i < 64) ? kp0 : (i < 128) ? kp1 : kp2;
        if ((kw >> (i & 63)) & 1ULL) {
            kp0 &= ~m0; kp1 &= ~m1; kp2 &= ~m2;
        }
    }

    for (int t = tid; t < M; t += 128) {
        int n = (int)(ks[t] & 0xFFFFFFFFULL);
        int idx = bIdx + n;
        ull kw = (t < 64) ? kp0 : (t < 128) ? kp1 : kp2;
        bool kept = (kw >> (t & 63)) & 1ULL;
        float s = __uint_as_float(~(unsigned)(ks[t] >> 32));
        float4 Bv = bx[t];
        out[idx * 5 + 0] = kept ? Bv.x : 0.0f;
        out[idx * 5 + 1] = kept ? Bv.y : 0.0f;
        out[idx * 5 + 2] = kept ? Bv.z : 0.0f;
        out[idx * 5 + 3] = kept ? Bv.w : 0.0f;
        out[idx * 5 + 4] = kept ? s : 0.0f;
        out[Bn * Nn * 6 + idx] = kept ? 1.0f : 0.0f;
    }
}

// ---------------- launch -----------------------------------------------------
extern "C" void kernel_launch(void* const* d_in, const int* in_sizes, int n_in,
                              void* d_out, int out_size)
{
    const float* feat = (const float*)d_in[0];
    const float* wo   = (const float*)d_in[1];
    const float* bo   = (const float*)d_in[2];
    const float* wc   = (const float*)d_in[3];
    const float* bc   = (const float*)d_in[4];
    const float* wr   = (const float*)d_in[5];
    const float* br   = (const float*)d_in[6];
    float* out = (float*)d_out;

    size_t smem = (size_t)F_TOTAL * sizeof(float);   // 57472 B
    cudaFuncSetAttribute(head_kernel,
                         cudaFuncAttributeMaxDynamicSharedMemorySize, (int)smem);

    head_kernel<<<400, TBH, smem>>>(feat, wo, bo, wc, bc, wr, br, out);
    nms_kernel<<<NGRP, 128>>>(out);
}